// round 17
// baseline (speedup 1.0000x reference)
#include <cuda_runtime.h>
#include <cuda_fp16.h>
#include <cstdint>

// ---------------- problem constants ----------------
#define BQ    8
#define HWQ   6400          // 80*80
#define MTOT  51200         // 8*6400
#define K1    1024
#define N1    256
#define K2    256
#define N2    1024
#define NSEG  25            // 6400 / 256

// ---------------- scratch (device globals) --------
__device__ __align__(16) __half g_W1h[N1 * K1];      // [n][k] fp16 (DWT+BN1 folded)
__device__ __align__(16) float  g_bias1[N1];
__device__ __align__(16) __half g_W2h[N2 * K2];      // [j][k] fp16 (BN2 folded, permuted)
__device__ __align__(16) float  g_bias2p[N2];
__device__ __align__(16) float  g_cmap[BQ * 256];
__device__ __align__(16) __half g_fused[(long)MTOT * 256];  // fp16 (26 MB)
__device__ __align__(16) float  g_avg_sp[MTOT];
__device__ __align__(16) float  g_max_sp[MTOT];
__device__ __align__(16) float  g_gate[MTOT];
__device__ __align__(16) float  g_chsum_part[NSEG * BQ * 256];
__device__ __align__(16) float  g_chmax_part[NSEG * BQ * 256];

// ---------------- PTX helpers ----------------------
__device__ __forceinline__ uint32_t smem_u32(const void* p) {
    uint32_t a;
    asm("{ .reg .u64 t; cvta.to.shared.u64 t, %1; cvt.u32.u64 %0, t; }" : "=r"(a) : "l"(p));
    return a;
}
__device__ __forceinline__ void ldsm4(uint32_t* r, uint32_t addr) {
    asm volatile("ldmatrix.sync.aligned.m8n8.x4.shared.b16 {%0,%1,%2,%3}, [%4];"
                 : "=r"(r[0]), "=r"(r[1]), "=r"(r[2]), "=r"(r[3]) : "r"(addr));
}
__device__ __forceinline__ void ldsm4t(uint32_t* r, uint32_t addr) {
    asm volatile("ldmatrix.sync.aligned.m8n8.x4.trans.shared.b16 {%0,%1,%2,%3}, [%4];"
                 : "=r"(r[0]), "=r"(r[1]), "=r"(r[2]), "=r"(r[3]) : "r"(addr));
}
__device__ __forceinline__ void mma16(float* d, const uint32_t* a, uint32_t b0, uint32_t b1) {
    asm volatile(
        "mma.sync.aligned.m16n8k16.row.col.f32.f16.f16.f32 "
        "{%0,%1,%2,%3}, {%4,%5,%6,%7}, {%8,%9}, {%0,%1,%2,%3};"
        : "+f"(d[0]), "+f"(d[1]), "+f"(d[2]), "+f"(d[3])
        : "r"(a[0]), "r"(a[1]), "r"(a[2]), "r"(a[3]), "r"(b0), "r"(b1));
}
__device__ __forceinline__ void cpa16(uint32_t dst, const void* src) {
    asm volatile("cp.async.cg.shared.global [%0], [%1], 16;" :: "r"(dst), "l"(src));
}
#define CP_COMMIT asm volatile("cp.async.commit_group;" ::: "memory")
#define CP_WAIT1  asm volatile("cp.async.wait_group 1;" ::: "memory")
#define CP_WAIT0  asm volatile("cp.async.wait_group 0;" ::: "memory")

// ---------------- prep (R14): fold DWT+BN1 into W1; BN2+permute into W2 ---
__global__ void prep(const float* __restrict__ fw, const float* __restrict__ fb,
                     const float* __restrict__ g1, const float* __restrict__ b1,
                     const float* __restrict__ m1, const float* __restrict__ v1,
                     const float* __restrict__ pw, const float* __restrict__ pb,
                     const float* __restrict__ g2, const float* __restrict__ b2,
                     const float* __restrict__ m2, const float* __restrict__ v2) {
    int idx = blockIdx.x * blockDim.x + threadIdx.x;
    if (idx < K1 * N1) {
        int o = idx & 255;
        int k = idx >> 8;            // k = c*4 + q, q = 2*dy + dx
        int c = k >> 2, q = k & 3;
        float inv = g1[o] * rsqrtf(v1[o] + 1e-5f);
        float slh = (q < 2) ? 1.f : -1.f;
        float shl = ((q & 1) == 0) ? 1.f : -1.f;
        float shh = slh * shl;
        float val = fw[o * 1024 + c]
                  + slh * fw[o * 1024 + 256 + c]
                  + shl * fw[o * 1024 + 512 + c]
                  + shh * fw[o * 1024 + 768 + c];
        g_W1h[o * 1024 + k] = __float2half_rn(0.5f * inv * val);
        if (k == 0) g_bias1[o] = fb[o] * inv + b1[o] - m1[o] * inv;
    } else {
        int idx2 = idx - K1 * N1;
        int j = idx2 & 1023;          // j = c'*4 + g
        int k = idx2 >> 10;
        int o = (j & 3) * 256 + (j >> 2);
        float inv = g2[o] * rsqrtf(v2[o] + 1e-5f);
        g_W2h[j * 256 + k] = __float2half_rn(pw[o * 256 + k] * inv);
        if (k == 0) g_bias2p[j] = pb[o] * inv + b2[o] - m2[o] * inv;
    }
}

// ============================================================================
// GEMM1 (R14 verbatim, proven 124us)
// ============================================================================
#define G1_SMEM 167936
__global__ __launch_bounds__(512) void gemm1(const float* __restrict__ x) {
    extern __shared__ char smem[];
    const uint32_t sb = smem_u32(smem);
    const int tid = threadIdx.x;
    const int lane = tid & 31, warp = tid >> 5;
    const int wm = warp & 3, wn = warp >> 2;
    const int m0 = blockIdx.x * 128;
    const int bb = m0 / HWQ;
    const int hw0 = m0 % HWQ;

    if (tid < 64) ((float4*)(smem + 162816))[tid] = ((const float4*)g_bias1)[tid];

    const int cA = tid >> 7;
    const int dyA = (tid >> 6) & 1;
    const int mlA = (tid & 63) * 2;
    const int hwA = hw0 + mlA;
    const int hA = hwA / 80, wA = hwA - hA * 80;
    const float* aBase = x + (long)bb * 256 * 25600 + cA * 25600 + (2 * hA + dyA) * 160 + 2 * wA;
    const int aRowOff = (cA * 4 + dyA * 2) * 272 + mlA * 2;   // bytes

    const int rowB = tid >> 1;
    const int colH = (tid & 1) * 32;
    const __half* bSrcBase = g_W1h + rowB * 1024 + colH;
    const uint32_t bDstOff = (uint32_t)(rowB * 144 + colH * 2);

    const uint32_t aLd = sb
        + (uint32_t)(((lane & 7) + ((lane >> 4) << 3)) * 272
                     + (wm * 32 + ((lane >> 3) & 1) * 8) * 2);
    const uint32_t bLd = sb + 52224u + (uint32_t)((wn * 64 + (lane & 15)) * 144 + (lane >> 4) * 16);

    float acc[2][8][4];
#pragma unroll
    for (int a = 0; a < 2; a++)
#pragma unroll
        for (int b = 0; b < 8; b++)
#pragma unroll
            for (int c = 0; c < 4; c++) acc[a][b][c] = 0.f;

    float4 aP[4];
#pragma unroll
    for (int i = 0; i < 4; ++i) aP[i] = *(const float4*)(aBase + i * 4 * 25600);
    {
        char* aSt = smem + aRowOff;
#pragma unroll
        for (int i = 0; i < 4; ++i) {
            *(__half2*)(aSt + i * 16 * 272)       = __floats2half2_rn(aP[i].x, aP[i].z);
            *(__half2*)(aSt + i * 16 * 272 + 272) = __floats2half2_rn(aP[i].y, aP[i].w);
        }
    }
#pragma unroll
    for (int i = 0; i < 4; ++i) aP[i] = *(const float4*)(aBase + 409600 + i * 4 * 25600);
    {
        uint32_t bD = sb + 52224u + bDstOff;
        const __half* bS = bSrcBase;
        cpa16(bD, bS); cpa16(bD + 16, bS + 8); cpa16(bD + 32, bS + 16); cpa16(bD + 48, bS + 24);
        CP_COMMIT;
        bD = sb + 52224u + 36864u + bDstOff;
        bS = bSrcBase + 64;
        cpa16(bD, bS); cpa16(bD + 16, bS + 8); cpa16(bD + 32, bS + 16); cpa16(bD + 48, bS + 24);
        CP_COMMIT;
    }

    for (int it = 0; it < 16; ++it) {
        if (it < 15) { CP_WAIT1; } else { CP_WAIT0; }
        __syncthreads();
        if (it < 15) {
            char* aSt = smem + ((it + 1) % 3) * 17408 + aRowOff;
#pragma unroll
            for (int i = 0; i < 4; ++i) {
                *(__half2*)(aSt + i * 16 * 272)       = __floats2half2_rn(aP[i].x, aP[i].z);
                *(__half2*)(aSt + i * 16 * 272 + 272) = __floats2half2_rn(aP[i].y, aP[i].w);
            }
        }
        if (it < 14) {
            uint32_t bD = sb + 52224u + (uint32_t)(((it + 2) % 3) * 36864) + bDstOff;
            const __half* bS = bSrcBase + (it + 2) * 64;
            cpa16(bD, bS); cpa16(bD + 16, bS + 8); cpa16(bD + 32, bS + 16); cpa16(bD + 48, bS + 24);
            CP_COMMIT;
#pragma unroll
            for (int i = 0; i < 4; ++i)
                aP[i] = *(const float4*)(aBase + (long)(it + 2) * 409600 + i * 4 * 25600);
        }
        const uint32_t aB = aLd + (uint32_t)((it % 3) * 17408);
        const uint32_t bB = bLd + (uint32_t)((it % 3) * 36864);
#pragma unroll
        for (int kk = 0; kk < 4; ++kk) {
            uint32_t af[2][4], bf[4][4];
            ldsm4t(af[0], aB + kk * 16 * 272);
            ldsm4t(af[1], aB + kk * 16 * 272 + 32);
#pragma unroll
            for (int i = 0; i < 4; ++i) ldsm4(bf[i], bB + kk * 32 + i * 16 * 144);
#pragma unroll
            for (int ms = 0; ms < 2; ++ms)
#pragma unroll
                for (int i = 0; i < 4; ++i) {
                    mma16(acc[ms][2 * i + 0], af[ms], bf[i][0], bf[i][2]);
                    mma16(acc[ms][2 * i + 1], af[ms], bf[i][1], bf[i][3]);
                }
        }
    }

    const float* biasS = (const float*)(smem + 162816);
    float* redS = (float*)(smem + 163840);
    float* redM = (float*)(smem + 165888);
    __half2* fh2 = (__half2*)g_fused;
    float rs[2][2] = {{0.f, 0.f}, {0.f, 0.f}};
    float rm[2][2] = {{0.f, 0.f}, {0.f, 0.f}};
#pragma unroll
    for (int ms = 0; ms < 2; ++ms) {
        int row0 = m0 + wm * 32 + ms * 16 + (lane >> 2);
#pragma unroll
        for (int ns = 0; ns < 8; ++ns) {
            int col = wn * 64 + ns * 8 + (lane & 3) * 2;
            float b0 = biasS[col], b1 = biasS[col + 1];
            float v0 = fmaxf(acc[ms][ns][0] + b0, 0.f);
            float v1 = fmaxf(acc[ms][ns][1] + b1, 0.f);
            fh2[(long)row0 * 128 + (col >> 1)] = __floats2half2_rn(v0, v1);
            rs[ms][0] += v0 + v1;
            rm[ms][0] = fmaxf(rm[ms][0], fmaxf(v0, v1));
            float v2 = fmaxf(acc[ms][ns][2] + b0, 0.f);
            float v3 = fmaxf(acc[ms][ns][3] + b1, 0.f);
            fh2[(long)(row0 + 8) * 128 + (col >> 1)] = __floats2half2_rn(v2, v3);
            rs[ms][1] += v2 + v3;
            rm[ms][1] = fmaxf(rm[ms][1], fmaxf(v2, v3));
        }
    }
#pragma unroll
    for (int ms = 0; ms < 2; ++ms)
#pragma unroll
        for (int hf = 0; hf < 2; ++hf) {
            float s = rs[ms][hf], mx = rm[ms][hf];
            s += __shfl_xor_sync(0xffffffffu, s, 1);
            s += __shfl_xor_sync(0xffffffffu, s, 2);
            mx = fmaxf(mx, __shfl_xor_sync(0xffffffffu, mx, 1));
            mx = fmaxf(mx, __shfl_xor_sync(0xffffffffu, mx, 2));
            if ((lane & 3) == 0) {
                int r_l = wm * 32 + ms * 16 + (lane >> 2) + hf * 8;
                redS[r_l * 4 + wn] = s;
                redM[r_l * 4 + wn] = mx;
            }
        }
    __syncthreads();
    if (tid < 128) {
        float s = redS[tid * 4] + redS[tid * 4 + 1] + redS[tid * 4 + 2] + redS[tid * 4 + 3];
        float mx = fmaxf(fmaxf(redM[tid * 4], redM[tid * 4 + 1]),
                         fmaxf(redM[tid * 4 + 2], redM[tid * 4 + 3]));
        g_avg_sp[m0 + tid] = s * (1.f / 256.f);
        g_max_sp[m0 + tid] = mx;
    }
}

// ============================================================================
// spstats (R14 verbatim)
// ============================================================================
__global__ void spstats(const float* __restrict__ sa_w) {
    __shared__ float sw[98];
    __shared__ float avgS[800], maxS[800];
    __shared__ float gate_s[256];
    __shared__ float ss[512], mm_[512];
    const int tid = threadIdx.x;
    if (tid < 98) sw[tid] = sa_w[tid];
    const int m0 = blockIdx.x * 256;
    const int bb = m0 / HWQ;
    const int s0 = m0 % HWQ;
    const int h0 = s0 / 80;
    const int baseP = (h0 - 3) * 80;
    for (int t = tid; t < 800; t += 256) {
        int p = baseP + t;
        float a = 0.f, mx = 0.f;
        if ((unsigned)p < (unsigned)HWQ) {
            int mi = bb * HWQ + p;
            a = g_avg_sp[mi];
            mx = g_max_sp[mi];
        }
        avgS[t] = a;
        maxS[t] = mx;
    }
    __syncthreads();
    {
        int s = s0 + tid;
        int h = s / 80, w = s % 80;
        float acc = 0.f;
#pragma unroll
        for (int ky = 0; ky < 7; ky++) {
            int y = h + ky - 3;
            if ((unsigned)y < 80u) {
                int lrow = (y - (h0 - 3)) * 80;
#pragma unroll
                for (int kx = 0; kx < 7; kx++) {
                    int xx = w + kx - 3;
                    if ((unsigned)xx < 80u)
                        acc += avgS[lrow + xx] * sw[ky * 7 + kx]
                             + maxS[lrow + xx] * sw[49 + ky * 7 + kx];
                }
            }
        }
        float g = 1.f / (1.f + expf(-acc));
        g_gate[m0 + tid] = g;
        gate_s[tid] = g;
    }
    __syncthreads();
    const int c2 = tid & 127;
    const int rp = tid >> 7;
    const __half2* fh = (const __half2*)g_fused;
    float s0f = 0.f, s1f = 0.f, x0 = 0.f, x1 = 0.f;
#pragma unroll 4
    for (int r = rp; r < 256; r += 2) {
        float gg = gate_s[r];
        float2 f = __half22float2(fh[(long)(m0 + r) * 128 + c2]);
        float a = gg * f.x, b = gg * f.y;
        s0f += a; s1f += b;
        x0 = fmaxf(x0, a); x1 = fmaxf(x1, b);
    }
    ss[(2 * c2 + 0) * 2 + rp] = s0f;
    ss[(2 * c2 + 1) * 2 + rp] = s1f;
    mm_[(2 * c2 + 0) * 2 + rp] = x0;
    mm_[(2 * c2 + 1) * 2 + rp] = x1;
    __syncthreads();
    const int seg = (m0 % HWQ) >> 8;
    float s = ss[tid * 2] + ss[tid * 2 + 1];
    float mx = fmaxf(mm_[tid * 2], mm_[tid * 2 + 1]);
    g_chsum_part[(seg * BQ + bb) * 256 + tid] = s;
    g_chmax_part[(seg * BQ + bb) * 256 + tid] = mx;
}

// ---------------- chmap: per-batch channel MLP -> g_cmap (grid 8) ---------
__global__ void chmap_k(const float* __restrict__ ca_w1,
                        const float* __restrict__ ca_w2) {
    const int bb = blockIdx.x;
    const int tid = threadIdx.x;
    __shared__ float sA[256], sM[256], sH[32];
    {
        float s = 0.f, mx = 0.f;
#pragma unroll
        for (int seg = 0; seg < NSEG; seg++) {
            s += g_chsum_part[(seg * BQ + bb) * 256 + tid];
            mx = fmaxf(mx, g_chmax_part[(seg * BQ + bb) * 256 + tid]);
        }
        sA[tid] = s * (1.f / 6400.f);
        sM[tid] = mx;
    }
    __syncthreads();
    {
        int wq = tid >> 5, ln = tid & 31;
#pragma unroll
        for (int it = 0; it < 4; it++) {
            int t = wq * 4 + it;
            int u = t & 15, which = t >> 4;
            const float* vec = which ? sM : sA;
            float d = 0.f;
            for (int cc = ln; cc < 256; cc += 32) d += ca_w1[u * 256 + cc] * vec[cc];
#pragma unroll
            for (int off = 16; off; off >>= 1) d += __shfl_xor_sync(0xffffffffu, d, off);
            if (ln == 0) sH[t] = fmaxf(d, 0.f);
        }
    }
    __syncthreads();
    {
        float o = 0.f;
#pragma unroll
        for (int u = 0; u < 16; u++) o += ca_w2[tid * 16 + u] * (sH[u] + sH[16 + u]);
        g_cmap[bb * 256 + tid] = 1.f / (1.f + expf(-o));
    }
}

// ============================================================================
// GEMM2 (fp16 HMMA k16): 256 thr, 2 CTAs/SM. CTA 64m x 256n-block (4 blocks),
// 8 warps 2m x 4n, warp tile 32x64. A resident full-K (64 x 264h, gate+cmap
// folded at fill). B = g_W2h, 2-stage cp.async (dist-1; co-resident CTA
// covers the wait). Epilogue: 2 half-passes of 128 j through the dead B
// stage ([j][64m] fp32, 272B rows): STS -> bar -> per-channel iDWT (float4
// LDS, 8 px/lane) + coalesced x/out float4 -> bar. 5 barriers per n-block.
// smem: A@0(33792) B 2x36864 @33792(73728) bias@107520(4096)
//       cmap@111616(1024) gate@112640(256)  total 112896 -> 2 CTAs/SM
// ============================================================================
#define G2_SMEM 112896
__global__ __launch_bounds__(256, 2) void gemm2(const float* __restrict__ x,
                                                float* __restrict__ out) {
    extern __shared__ char smem[];
    const uint32_t sb = smem_u32(smem);
    const int tid = threadIdx.x;
    const int lane = tid & 31, warp = tid >> 5;
    const int wm = warp & 1, wn = warp >> 1;
    const int m0 = blockIdx.x * 64;
    const int bb = m0 / HWQ;
    const int hw0 = m0 % HWQ;

    float* biasS = (float*)(smem + 107520);
    float* cmapS = (float*)(smem + 111616);
    float* gateS = (float*)(smem + 112640);
    ((float4*)biasS)[tid] = ((const float4*)g_bias2p)[tid];
    if (tid < 64) ((float4*)cmapS)[tid] = ((const float4*)(g_cmap + bb * 256))[tid];
    if (tid < 16) ((float4*)gateS)[tid] = ((const float4*)(g_gate + m0))[tid];

    // ---- epilogue constants: lane covers 8 px of one channel
    const int hwE = hw0 + (lane & 7) * 8;
    const int hE = hwE / 80, wE = hwE - hE * 80;
    const long rowT = ((long)(2 * hE)) * 160 + 2 * wE;

    // ---- B cp.async: 256 rows x 128B per chunk, 1 row/thread
    const uint32_t bDstOff = (uint32_t)(tid * 144);

    // prologue: B(0) -> stage0
    {
        uint32_t bD = sb + 33792u + bDstOff;
        const __half* bS = g_W2h + tid * 256;     // nn=0: nb=0, kc=0
#pragma unroll
        for (int i = 0; i < 8; ++i) cpa16(bD + i * 16, bS + i * 8);
        CP_COMMIT;
    }
    __syncthreads();    // gate/cmap visible

    // ---- fill resident A: fused(fp16) * gate * cmap -> fp16 (264h rows)
    {
        const int kqA = tid & 63;            // channels kqA*4..+3
        const int ml0 = tid >> 6;            // 0..3
        const __half2* fh = (const __half2*)g_fused;
#pragma unroll
        for (int i = 0; i < 16; ++i) {
            int m_l = ml0 + i * 4;
            float2 f01 = __half22float2(fh[(long)(m0 + m_l) * 128 + kqA * 2]);
            float2 f23 = __half22float2(fh[(long)(m0 + m_l) * 128 + kqA * 2 + 1]);
            float gm = gateS[m_l];
            f01.x *= gm * cmapS[kqA * 4 + 0];
            f01.y *= gm * cmapS[kqA * 4 + 1];
            f23.x *= gm * cmapS[kqA * 4 + 2];
            f23.y *= gm * cmapS[kqA * 4 + 3];
            *(__half2*)(smem + m_l * 528 + kqA * 8)     = __floats2half2_rn(f01.x, f01.y);
            *(__half2*)(smem + m_l * 528 + kqA * 8 + 4) = __floats2half2_rn(f23.x, f23.y);
        }
    }

    const uint32_t aLd = sb + (uint32_t)((wm * 32 + (lane & 15)) * 528 + (lane >> 4) * 16);
    const uint32_t bLd = sb + 33792u + (uint32_t)((wn * 64 + (lane & 15)) * 144 + (lane >> 4) * 16);

    float acc[2][8][4];
#pragma unroll
    for (int a = 0; a < 2; a++)
#pragma unroll
        for (int b = 0; b < 8; b++)
#pragma unroll
            for (int c = 0; c < 4; c++) acc[a][b][c] = 0.f;

    for (int it = 0; it < 16; ++it) {    // it = nb*4 + kc
        const int kc = it & 3;
        CP_WAIT0;
        __syncthreads();                 // B(it) (+ A fill at it=0) visible
        if (it < 15) {                   // B(it+1) -> stage (it+1)&1
            int nn = it + 1;
            uint32_t bD = sb + 33792u + (uint32_t)((nn & 1) * 36864) + bDstOff;
            const __half* bS = g_W2h + ((nn >> 2) * 256 + tid) * 256 + (nn & 3) * 64;
#pragma unroll
            for (int i = 0; i < 8; ++i) cpa16(bD + i * 16, bS + i * 8);
            CP_COMMIT;
        }
        const uint32_t aB = aLd + (uint32_t)(kc * 128);   // kc * 64 halves
        const uint32_t bB = bLd + (uint32_t)((it & 1) * 36864);
#pragma unroll
        for (int kk = 0; kk < 4; ++kk) {
            uint32_t af[2][4], bf[4][4];
            ldsm4(af[0], aB + kk * 32);
            ldsm4(af[1], aB + kk * 32 + 16 * 528);
#pragma unroll
            for (int i = 0; i < 4; ++i) ldsm4(bf[i], bB + kk * 32 + i * 16 * 144);
#pragma unroll
            for (int ms = 0; ms < 2; ++ms)
#pragma unroll
                for (int i = 0; i < 4; ++i) {
                    mma16(acc[ms][2 * i + 0], af[ms], bf[i][0], bf[i][2]);
                    mma16(acc[ms][2 * i + 1], af[ms], bf[i][1], bf[i][3]);
                }
        }
        if (kc == 3) {
            // ==== staged epilogue for n-block nb; scratch = dead B stage
            // it&1 (its next writer, B(it+2), is issued only after the next
            // loop iteration's barrier). B(it+1) is in the OTHER stage. ====
            __syncthreads();             // all ldsm reads of stage it&1 done
            const int nb = it >> 2;
            char* stgp = smem + 33792 + (it & 1) * 36864;
#pragma unroll
            for (int hh = 0; hh < 2; ++hh) {   // half: j in [hh*128, +128)
                // --- STS: warps with wn in {2hh, 2hh+1}
                if ((wn >> 1) == hh) {
                    const int jbase = (wn & 1) * 64;
#pragma unroll
                    for (int ns = 0; ns < 8; ++ns) {
                        int jc = nb * 256 + wn * 64 + ns * 8 + (lane & 3) * 2;
                        float b0 = biasS[jc], b1 = biasS[jc + 1];
                        int jp = jbase + ns * 8 + (lane & 3) * 2;
#pragma unroll
                        for (int ms = 0; ms < 2; ++ms)
#pragma unroll
                            for (int hf = 0; hf < 2; ++hf) {
                                int m_l = wm * 32 + ms * 16 + (lane >> 2) + hf * 8;
                                float v0 = fmaxf(acc[ms][ns][hf * 2 + 0] + b0, 0.f);
                                float v1 = fmaxf(acc[ms][ns][hf * 2 + 1] + b1, 0.f);
                                *(float*)(stgp + jp * 272 + m_l * 4) = v0;
                                *(float*)(stgp + (jp + 1) * 272 + m_l * 4) = v1;
                            }
                    }
                }
                // --- identity prefetch: channel cp, 8 px starting at lane&7
                const int chl = warp * 4 + (lane >> 3);    // 0..31 in half
                const int cp = nb * 64 + hh * 32 + chl;
                const float* xp = x + ((long)(bb * 256 + cp)) * 25600 + rowT;
                float4 xt0 = *(const float4*)(xp);
                float4 xt1 = *(const float4*)(xp + 4);
                float4 xt2 = *(const float4*)(xp + 8);
                float4 xt3 = *(const float4*)(xp + 12);
                float4 xb0 = *(const float4*)(xp + 160);
                float4 xb1 = *(const float4*)(xp + 164);
                float4 xb2 = *(const float4*)(xp + 168);
                float4 xb3 = *(const float4*)(xp + 172);
                __syncthreads();
                // --- read 4 wavelet rows (8 px each), iDWT, +identity, store
                char* rb = stgp + (chl * 4) * 272 + (lane & 7) * 32;
                float4 A0 = *(const float4*)(rb);
                float4 A1 = *(const float4*)(rb + 16);
                float4 B0 = *(const float4*)(rb + 272);
                float4 B1 = *(const float4*)(rb + 288);
                float4 C0 = *(const float4*)(rb + 544);
                float4 C1 = *(const float4*)(rb + 560);
                float4 D0 = *(const float4*)(rb + 816);
                float4 D1 = *(const float4*)(rb + 832);
                float* op = out + ((long)(bb * 256 + cp)) * 25600 + rowT;
                float4 t, b;
#define IDWT2(LL0, LH0, HL0, HH0, LL1, LH1, HL1, HH1, XT, XB, OT, OB)          \
                {                                                              \
                    float pa = (LL0) + (LH0), ra = (LL0) - (LH0);              \
                    float pb = (HL0) + (HH0), rb_ = (HL0) - (HH0);             \
                    t.x = 0.5f * (pa + pb) + (XT).x;                           \
                    t.y = 0.5f * (pa - pb) + (XT).y;                           \
                    b.x = 0.5f * (ra + rb_) + (XB).x;                          \
                    b.y = 0.5f * (ra - rb_) + (XB).y;                          \
                    pa = (LL1) + (LH1); ra = (LL1) - (LH1);                    \
                    pb = (HL1) + (HH1); rb_ = (HL1) - (HH1);                   \
                    t.z = 0.5f * (pa + pb) + (XT).z;                           \
                    t.w = 0.5f * (pa - pb) + (XT).w;                           \
                    b.z = 0.5f * (ra + rb_) + (XB).z;                          \
                    b.w = 0.5f * (ra - rb_) + (XB).w;                          \
                    *(float4*)(OT) = t;                                        \
                    *(float4*)(OB) = b;                                        \
                }
                IDWT2(A0.x, B0.x, C0.x, D0.x, A0.y, B0.y, C0.y, D0.y,
                      xt0, xb0, op, op + 160);
                IDWT2(A0.z, B0.z, C0.z, D0.z, A0.w, B0.w, C0.w, D0.w,
                      xt1, xb1, op + 4, op + 164);
                IDWT2(A1.x, B1.x, C1.x, D1.x, A1.y, B1.y, C1.y, D1.y,
                      xt2, xb2, op + 8, op + 168);
                IDWT2(A1.z, B1.z, C1.z, D1.z, A1.w, B1.w, C1.w, D1.w,
                      xt3, xb3, op + 12, op + 172);
#undef IDWT2
                __syncthreads();
            }
#pragma unroll
            for (int a = 0; a < 2; a++)
#pragma unroll
                for (int b2 = 0; b2 < 8; b2++)
#pragma unroll
                    for (int c = 0; c < 4; c++) acc[a][b2][c] = 0.f;
        }
    }
}

// ---------------- host launch ---------------------------------------------
extern "C" void kernel_launch(void* const* d_in, const int* in_sizes, int n_in,
                              void* d_out, int out_size) {
    (void)in_sizes; (void)n_in; (void)out_size;
    const float* x        = (const float*)d_in[0];
    const float* fusion_w = (const float*)d_in[1];
    const float* fusion_b = (const float*)d_in[2];
    const float* bn1_g    = (const float*)d_in[3];
    const float* bn1_b    = (const float*)d_in[4];
    const float* bn1_m    = (const float*)d_in[5];
    const float* bn1_v    = (const float*)d_in[6];
    const float* sa_w     = (const float*)d_in[7];
    const float* ca_w1    = (const float*)d_in[8];
    const float* ca_w2    = (const float*)d_in[9];
    const float* proj_w   = (const float*)d_in[10];
    const float* proj_b   = (const float*)d_in[11];
    const float* bn2_g    = (const float*)d_in[12];
    const float* bn2_b    = (const float*)d_in[13];
    const float* bn2_m    = (const float*)d_in[14];
    const float* bn2_v    = (const float*)d_in[15];
    float* out = (float*)d_out;

    cudaFuncSetAttribute(gemm1, cudaFuncAttributeMaxDynamicSharedMemorySize, G1_SMEM);
    cudaFuncSetAttribute(gemm2, cudaFuncAttributeMaxDynamicSharedMemorySize, G2_SMEM);

    prep<<<(2 * K1 * N1) / 256, 256>>>(fusion_w, fusion_b, bn1_g, bn1_b, bn1_m, bn1_v,
                                       proj_w, proj_b, bn2_g, bn2_b, bn2_m, bn2_v);
    gemm1<<<MTOT / 128, 512, G1_SMEM>>>(x);
    spstats<<<MTOT / 256, 256>>>(sa_w);
    chmap_k<<<BQ, 256>>>(ca_w1, ca_w2);
    gemm2<<<MTOT / 64, 256, G2_SMEM>>>(x, out);
}